// round 11
// baseline (speedup 1.0000x reference)
#include <cuda_runtime.h>
#include <cuda_bf16.h>

// FWHT-4096 / sqrt(4096). R4 bit-group schedule + streaming cache policy +
// vectorized (LDS.128/STS.128) round-2 smem pass.
//
// Index i = Q*1024 + P*128 + D*32 + L  (Q:i[10:12], P:i[7:10], D:i[5:7], L:i[0:5])
// Round 1: H32 over (Q,P)=i[7:12] in regs  (loads:  lanes = j, ideal coalescing)
// Round 2: H32 over L=i[0:5]      in regs  (smem, float4 in-place, conflict-free)
// Round 3: H4  over D=i[5:7]      in regs  (stores: lanes = L, ideal coalescing)
// Hadamard bit-stages commute -> equals the reference 12-stage FWHT.
//
// Smem strides (words): L:1, D:36 (==4 mod 32), P:144 (==16 mod 32), Q:1152 (==0)
//   W1 scalar  (lanes L):            banks = L + const                -> CF
//   R2 128-bit (8-lane phase group): word offs 16P+4D = {0,4,..,28}   -> CF
//   R3 scalar  (lanes L):            banks = L + 16P + 4D             -> CF

#define FWHT_N 4096
#define ROW_THREADS 128
#define ROWS_PER_BLOCK 2
#define BLOCK_THREADS (ROW_THREADS * ROWS_PER_BLOCK)
#define S_D 36
#define S_P 144
#define S_Q 1152
#define S_ROW (4 * S_Q)   // 4608 floats per row (18.4 KB)

__device__ __forceinline__ void h32(float v[32]) {
#pragma unroll
    for (int h = 1; h < 32; h <<= 1) {
#pragma unroll
        for (int i = 0; i < 32; i++) {
            if (!(i & h)) {
                float a = v[i], b = v[i | h];
                v[i]     = a + b;
                v[i | h] = a - b;
            }
        }
    }
}

__global__ void __launch_bounds__(BLOCK_THREADS, 4)
fwht4096_kernel(const float* __restrict__ x, float* __restrict__ out) {
    __shared__ float s[ROWS_PER_BLOCK * S_ROW];

    const int tid = threadIdx.x;
    const int rib = tid >> 7;          // row in block
    const int j   = tid & 127;         // thread within row
    const size_t row = (size_t)blockIdx.x * ROWS_PER_BLOCK + rib;

    const float* __restrict__ xr = x + row * FWHT_N;
    float* __restrict__ orow     = out + row * FWHT_N;
    float* __restrict__ sr       = s + rib * S_ROW;

    float v[32];

    // ---- Round 1: regs = (Q,P). Streaming loads, lanes = j -> one line/warp. ----
#pragma unroll
    for (int r = 0; r < 32; r++) v[r] = __ldcs(xr + r * 128 + j);
    h32(v);   // transforms index bits 7..11

    // W1: thread (D,L) writes (Q,P)-indexed values. Lanes vary L -> conflict-free.
    {
        const int D = j >> 5, L = j & 31;
        float* w = sr + D * S_D + L;
#pragma unroll
        for (int r = 0; r < 32; r++) {
            const int Q = r >> 3, P = r & 7;
            w[Q * S_Q + P * S_P] = v[r];
        }
    }
    __syncthreads();

    // ---- Round 2: regs = L. Thread (Q,P,D) owns 32 consecutive floats.
    //      float4 in-place: 8x LDS.128 + 8x STS.128, conflict-free. ----
    {
        const int D = j & 3, P = (j >> 2) & 7, Q = j >> 5;
        float4* b4 = reinterpret_cast<float4*>(sr + Q * S_Q + P * S_P + D * S_D);
#pragma unroll
        for (int k = 0; k < 8; k++) {
            float4 t = b4[k];
            v[4 * k + 0] = t.x;
            v[4 * k + 1] = t.y;
            v[4 * k + 2] = t.z;
            v[4 * k + 3] = t.w;
        }
        h32(v);   // transforms index bits 0..4
#pragma unroll
        for (int k = 0; k < 8; k++) {
            float4 t;
            t.x = v[4 * k + 0];
            t.y = v[4 * k + 1];
            t.z = v[4 * k + 2];
            t.w = v[4 * k + 3];
            b4[k] = t;
        }
    }
    __syncthreads();

    // ---- Round 3: gather (P,D), H4 over D, streaming coalesced stores. ----
    {
        const int L = j & 31, Q = j >> 5;
        const float* b = sr + Q * S_Q + L;
#pragma unroll
        for (int r = 0; r < 32; r++) {
            const int P = r >> 2, D = r & 3;
            v[r] = b[P * S_P + D * S_D];   // lanes vary L -> conflict-free
        }
#pragma unroll
        for (int h = 1; h < 4; h <<= 1) {
#pragma unroll
            for (int i = 0; i < 32; i++) {
                if (!(i & h)) {
                    float a = v[i], c = v[i | h];
                    v[i]     = a + c;
                    v[i | h] = a - c;
                }
            }
        }
        const float scale = 1.0f / 64.0f;   // 1/sqrt(4096)
        float* o = orow + Q * 1024 + L;
        // store addr = Q*1024 + P*128 + D*32 + L; lanes = L -> fully coalesced
#pragma unroll
        for (int r = 0; r < 32; r++) {
            const int P = r >> 2, D = r & 3;
            __stcs(o + P * 128 + D * 32, v[r] * scale);
        }
    }
}

extern "C" void kernel_launch(void* const* d_in, const int* in_sizes, int n_in,
                              void* d_out, int out_size) {
    const float* x = (const float*)d_in[0];
    float* out     = (float*)d_out;
    const int nrows = in_sizes[0] / FWHT_N;          // 16384
    const int grid  = nrows / ROWS_PER_BLOCK;        // 8192
    fwht4096_kernel<<<grid, BLOCK_THREADS>>>(x, out);
}

// round 13
// speedup vs baseline: 1.0151x; 1.0151x over previous
#include <cuda_runtime.h>
#include <cuda_bf16.h>

// FWHT-4096 / sqrt(4096). R10 (best measured: R4 bit-group schedule + streaming
// cache policy) with per-row named barriers: the two independent 128-thread row
// groups in a CTA sync separately (bar.sync 1/2, 128), letting their load/store
// bursts interleave with each other's smem phases and smoothing DRAM demand.
//
// Index i = Q*1024 + P*128 + D*32 + L  (Q:i[10:12], P:i[7:10], D:i[5:7], L:i[0:5])
// Round 1: H32 over (Q,P)=i[7:12] in regs  (loads:  lanes = j, ideal coalescing)
// Round 2: H32 over L=i[0:5]      in regs  (smem transpose, conflict-free)
// Round 3: H4  over D=i[5:7]      in regs  (stores: lanes = L, ideal coalescing)
// Hadamard bit-stages commute -> equals the reference 12-stage FWHT.

#define FWHT_N 4096
#define ROW_THREADS 128
#define ROWS_PER_BLOCK 2
#define BLOCK_THREADS (ROW_THREADS * ROWS_PER_BLOCK)
// smem strides: L:1, D:33 (==1 mod 32), P:132 (==4 mod 32), Q:1056 (==0 mod 32)
#define S_D 33
#define S_P 132
#define S_Q 1056
#define S_ROW (4 * S_Q)   // 4224 floats per row (16.9 KB)

// Named barrier scoped to one 128-thread row group (threads are warp-aligned
// and contiguous per group; ids 1/2 avoid the default barrier 0).
__device__ __forceinline__ void row_sync(int rib) {
    asm volatile("bar.sync %0, %1;" :: "r"(rib + 1), "n"(ROW_THREADS) : "memory");
}

__device__ __forceinline__ void h32(float v[32]) {
#pragma unroll
    for (int h = 1; h < 32; h <<= 1) {
#pragma unroll
        for (int i = 0; i < 32; i++) {
            if (!(i & h)) {
                float a = v[i], b = v[i | h];
                v[i]     = a + b;
                v[i | h] = a - b;
            }
        }
    }
}

__global__ void __launch_bounds__(BLOCK_THREADS, 4)
fwht4096_kernel(const float* __restrict__ x, float* __restrict__ out) {
    __shared__ float s[ROWS_PER_BLOCK * S_ROW];

    const int tid = threadIdx.x;
    const int rib = tid >> 7;          // row in block
    const int j   = tid & 127;         // thread within row
    const size_t row = (size_t)blockIdx.x * ROWS_PER_BLOCK + rib;

    const float* __restrict__ xr = x + row * FWHT_N;
    float* __restrict__ orow     = out + row * FWHT_N;
    float* __restrict__ sr       = s + rib * S_ROW;

    float v[32];

    // ---- Round 1: regs = (Q,P). Streaming loads, lanes = j -> one line/warp. ----
#pragma unroll
    for (int r = 0; r < 32; r++) v[r] = __ldcs(xr + r * 128 + j);
    h32(v);   // transforms index bits 7..11

    // W1: thread (D,L) writes (Q,P)-indexed values. Lanes vary L -> conflict-free.
    {
        const int D = j >> 5, L = j & 31;
        float* w = sr + D * S_D + L;
#pragma unroll
        for (int r = 0; r < 32; r++) {
            const int Q = r >> 3, P = r & 7;
            w[Q * S_Q + P * S_P] = v[r];
        }
    }
    row_sync(rib);

    // ---- Round 2: regs = L. Thread (Q,P,D): j = Q*32 + P*4 + D. In-place. ----
    {
        const int D = j & 3, P = (j >> 2) & 7, Q = j >> 5;
        float* b = sr + Q * S_Q + P * S_P + D * S_D;
        // banks = 4P + D + L mod 32: lanes (P,D) cover 0..31 -> conflict-free
#pragma unroll
        for (int L = 0; L < 32; L++) v[L] = b[L];
        h32(v);   // transforms index bits 0..4
#pragma unroll
        for (int L = 0; L < 32; L++) b[L] = v[L];
    }
    row_sync(rib);

    // ---- Round 3: gather (P,D), H4 over D, streaming coalesced stores. ----
    {
        const int L = j & 31, Q = j >> 5;
        const float* b = sr + Q * S_Q + L;
#pragma unroll
        for (int r = 0; r < 32; r++) {
            const int P = r >> 2, D = r & 3;
            v[r] = b[P * S_P + D * S_D];   // lanes vary L -> conflict-free
        }
#pragma unroll
        for (int h = 1; h < 4; h <<= 1) {
#pragma unroll
            for (int i = 0; i < 32; i++) {
                if (!(i & h)) {
                    float a = v[i], c = v[i | h];
                    v[i]     = a + c;
                    v[i | h] = a - c;
                }
            }
        }
        const float scale = 1.0f / 64.0f;   // 1/sqrt(4096)
        float* o = orow + Q * 1024 + L;
        // store addr = Q*1024 + P*128 + D*32 + L; lanes = L -> fully coalesced
#pragma unroll
        for (int r = 0; r < 32; r++) {
            const int P = r >> 2, D = r & 3;
            __stcs(o + P * 128 + D * 32, v[r] * scale);
        }
    }
}

extern "C" void kernel_launch(void* const* d_in, const int* in_sizes, int n_in,
                              void* d_out, int out_size) {
    const float* x = (const float*)d_in[0];
    float* out     = (float*)d_out;
    const int nrows = in_sizes[0] / FWHT_N;          // 16384
    const int grid  = nrows / ROWS_PER_BLOCK;        // 8192
    fwht4096_kernel<<<grid, BLOCK_THREADS>>>(x, out);
}

// round 14
// speedup vs baseline: 1.0239x; 1.0086x over previous
#include <cuda_runtime.h>
#include <cuda_bf16.h>

// FWHT-4096 / sqrt(4096). R4 bit-group schedule + streaming cache policy,
// 1 row per 128-thread CTA (10 CTAs/SM): finest CTA phase granularity so
// co-resident CTAs' load/compute/store phases interleave against the LTS cap.
//
// Index i = Q*1024 + P*128 + D*32 + L  (Q:i[10:12], P:i[7:10], D:i[5:7], L:i[0:5])
// Round 1: H32 over (Q,P)=i[7:12] in regs  (loads:  lanes = j, ideal coalescing)
// Round 2: H32 over L=i[0:5]      in regs  (smem transpose, conflict-free)
// Round 3: H4  over D=i[5:7]      in regs  (stores: lanes = L, ideal coalescing)
// Hadamard bit-stages commute -> equals the reference 12-stage FWHT.

#define FWHT_N 4096
#define ROW_THREADS 128
// smem strides: L:1, D:33 (==1 mod 32), P:132 (==4 mod 32), Q:1056 (==0 mod 32)
#define S_D 33
#define S_P 132
#define S_Q 1056
#define S_ROW (4 * S_Q)   // 4224 floats (16.9 KB)

__device__ __forceinline__ void h32(float v[32]) {
#pragma unroll
    for (int h = 1; h < 32; h <<= 1) {
#pragma unroll
        for (int i = 0; i < 32; i++) {
            if (!(i & h)) {
                float a = v[i], b = v[i | h];
                v[i]     = a + b;
                v[i | h] = a - b;
            }
        }
    }
}

__global__ void __launch_bounds__(ROW_THREADS, 8)
fwht4096_kernel(const float* __restrict__ x, float* __restrict__ out) {
    __shared__ float sr[S_ROW];

    const int j = threadIdx.x;
    const size_t row = blockIdx.x;

    const float* __restrict__ xr = x + row * FWHT_N;
    float* __restrict__ orow     = out + row * FWHT_N;

    float v[32];

    // ---- Round 1: regs = (Q,P). Streaming loads, lanes = j -> one line/warp. ----
#pragma unroll
    for (int r = 0; r < 32; r++) v[r] = __ldcs(xr + r * 128 + j);
    h32(v);   // transforms index bits 7..11

    // W1: thread (D,L) writes (Q,P)-indexed values. Lanes vary L -> conflict-free.
    {
        const int D = j >> 5, L = j & 31;
        float* w = sr + D * S_D + L;
#pragma unroll
        for (int r = 0; r < 32; r++) {
            const int Q = r >> 3, P = r & 7;
            w[Q * S_Q + P * S_P] = v[r];
        }
    }
    __syncthreads();

    // ---- Round 2: regs = L. Thread (Q,P,D): j = Q*32 + P*4 + D. In-place. ----
    {
        const int D = j & 3, P = (j >> 2) & 7, Q = j >> 5;
        float* b = sr + Q * S_Q + P * S_P + D * S_D;
        // banks = 4P + D + L mod 32: lanes (P,D) cover 0..31 -> conflict-free
#pragma unroll
        for (int L = 0; L < 32; L++) v[L] = b[L];
        h32(v);   // transforms index bits 0..4
#pragma unroll
        for (int L = 0; L < 32; L++) b[L] = v[L];
    }
    __syncthreads();

    // ---- Round 3: gather (P,D), H4 over D, streaming coalesced stores. ----
    {
        const int L = j & 31, Q = j >> 5;
        const float* b = sr + Q * S_Q + L;
#pragma unroll
        for (int r = 0; r < 32; r++) {
            const int P = r >> 2, D = r & 3;
            v[r] = b[P * S_P + D * S_D];   // lanes vary L -> conflict-free
        }
#pragma unroll
        for (int h = 1; h < 4; h <<= 1) {
#pragma unroll
            for (int i = 0; i < 32; i++) {
                if (!(i & h)) {
                    float a = v[i], c = v[i | h];
                    v[i]     = a + c;
                    v[i | h] = a - c;
                }
            }
        }
        const float scale = 1.0f / 64.0f;   // 1/sqrt(4096)
        float* o = orow + Q * 1024 + L;
        // store addr = Q*1024 + P*128 + D*32 + L; lanes = L -> fully coalesced
#pragma unroll
        for (int r = 0; r < 32; r++) {
            const int P = r >> 2, D = r & 3;
            __stcs(o + P * 128 + D * 32, v[r] * scale);
        }
    }
}

extern "C" void kernel_launch(void* const* d_in, const int* in_sizes, int n_in,
                              void* d_out, int out_size) {
    const float* x = (const float*)d_in[0];
    float* out     = (float*)d_out;
    const int nrows = in_sizes[0] / FWHT_N;   // 16384
    fwht4096_kernel<<<nrows, ROW_THREADS>>>(x, out);
}